// round 1
// baseline (speedup 1.0000x reference)
#include <cuda_runtime.h>
#include <math.h>

#define N_NODESC 20000
#define N_EDGESC 120000

// ---- static device scratch (no allocations allowed) ----
__device__ int   g_deg[N_NODESC];
__device__ int   g_off[N_NODESC + 1];
__device__ int   g_cursor[N_NODESC];
__device__ int   g_sorted[N_EDGESC];
__device__ float g_qd[N_NODESC * 16];        // qd scaled by c_logit
__device__ float g_R[N_NODESC * 384];        // R[n][j*24+u]
__device__ float g_expv[N_EDGESC];           // per sorted slot
__device__ float g_hy[N_EDGESC * 40];        // per sorted slot: h_v[16], y[24]

#define C_EMB   8.4335730690754870f     // 1.14136 * e^2
#define C_V     0.05103103630798287f    // 1/(4*sqrt(24))
#define C_LOGIT 0.003189439769248930f   // 1/(64*sqrt(24))

__device__ __forceinline__ float susf(float v) {
    return (v > 0.f) ? __expf(-__fdividef(1.f, v)) : 0.f;
}
__device__ __forceinline__ float siluf(float z) {
    return __fdividef(z, 1.f + __expf(-z));
}

// ---------------- CSR build ----------------
__global__ void k_zero() {
    int i = blockIdx.x * blockDim.x + threadIdx.x;
    if (i < N_NODESC) g_deg[i] = 0;
}

__global__ void k_hist(const int* __restrict__ dst) {
    int i = blockIdx.x * blockDim.x + threadIdx.x;
    if (i < N_EDGESC) atomicAdd(&g_deg[dst[i]], 1);
}

__global__ void k_scan() {
    __shared__ int s[1024];
    int tid = threadIdx.x;
    const int CH = (N_NODESC + 1023) / 1024;  // 20
    int base = tid * CH;
    int sum = 0;
    #pragma unroll
    for (int c = 0; c < CH; c++) {
        int idx = base + c;
        if (idx < N_NODESC) sum += g_deg[idx];
    }
    s[tid] = sum;
    __syncthreads();
    for (int d = 1; d < 1024; d <<= 1) {
        int v = (tid >= d) ? s[tid - d] : 0;
        __syncthreads();
        s[tid] += v;
        __syncthreads();
    }
    int run = s[tid] - sum;  // exclusive prefix
    for (int c = 0; c < CH; c++) {
        int idx = base + c;
        if (idx < N_NODESC) {
            g_off[idx] = run;
            g_cursor[idx] = run;
            run += g_deg[idx];
        }
    }
    if (tid == 1023) g_off[N_NODESC] = s[1023];
}

__global__ void k_scatter(const int* __restrict__ dst) {
    int i = blockIdx.x * blockDim.x + threadIdx.x;
    if (i < N_EDGESC) {
        int d = dst[i];
        int p = atomicAdd(&g_cursor[d], 1);
        g_sorted[p] = i;
    }
}

// ---------------- node precompute ----------------
// qd[n] = c_logit * ((x0[n] @ W_q / 4) @ W_dot)
__global__ void k_qd(const float* __restrict__ x,
                     const float* __restrict__ Wq,
                     const float* __restrict__ Wdot) {
    int n = blockIdx.x * blockDim.x + threadIdx.x;
    if (n >= N_NODESC) return;
    float x0[16], q[16];
    #pragma unroll
    for (int u = 0; u < 16; u++) x0[u] = x[n * 40 + u];
    #pragma unroll
    for (int w = 0; w < 16; w++) {
        float a = 0.f;
        #pragma unroll
        for (int u = 0; u < 16; u++) a += x0[u] * __ldg(&Wq[u * 16 + w]);
        q[w] = a * 0.25f;
    }
    #pragma unroll
    for (int w = 0; w < 16; w++) {
        float a = 0.f;
        #pragma unroll
        for (int u = 0; u < 16; u++) a += q[u] * __ldg(&Wdot[u * 16 + w]);
        g_qd[n * 16 + w] = a * C_LOGIT;
    }
}

// R[n][j*24+u] = sum_w Wk2[j*384 + u*16 + w] * qd[n][w]
__global__ void k_R(const float* __restrict__ Wk2) {
    __shared__ float qs[16];
    int n = blockIdx.x;
    int t = threadIdx.x;  // 0..383
    if (t < 16) qs[t] = g_qd[n * 16 + t];
    __syncthreads();
    int j = t / 24;
    int u = t - j * 24;
    const float* w = Wk2 + j * 384 + u * 16;
    float a = 0.f;
    #pragma unroll
    for (int k = 0; k < 16; k++) a += __ldg(&w[k]) * qs[k];
    g_R[n * 384 + t] = a;
}

// ---------------- pass A: per-edge logits / expv / (h_v, y) ----------------
__global__ void k_passA(const float* __restrict__ x, const float* __restrict__ pos,
                        const float* __restrict__ Wk1, const float* __restrict__ Wv1,
                        const int* __restrict__ src, const int* __restrict__ dst) {
    int i = blockIdx.x * blockDim.x + threadIdx.x;  // sorted slot
    if (i >= N_EDGESC) return;
    int e = g_sorted[i];
    int s = src[e], d = dst[e];

    float ev0 = pos[s * 3 + 0] - pos[d * 3 + 0];
    float ev1 = pos[s * 3 + 1] - pos[d * 3 + 1];
    float ev2 = pos[s * 3 + 2] - pos[d * 3 + 2];
    float elen = sqrtf(ev0 * ev0 + ev1 * ev1 + ev2 * ev2 + 1e-12f);

    float wcut = susf(10.f * (1.f - elen * 0.25f));
    if (!(wcut > 0.f)) { g_expv[i] = 0.f; return; }

    // radial basis: at most 2 active bins
    float t = elen * 2.75f;
    int b0 = (int)t;            // floor (t >= 0)
    float d0 = t - (float)b0;
    float g0 = (b0 >= 1 && b0 <= 10) ? (C_EMB * susf(d0 + 1.f) * susf(1.f - d0)) : 0.f;
    float g1 = (b0 >= 0 && b0 <= 9)  ? (C_EMB * susf(d0) * susf(2.f - d0)) : 0.f;
    int r0 = b0 - 1; if (r0 < 0) r0 = 0; if (r0 > 9) r0 = 9;
    int r1 = b0;     if (r1 < 0) r1 = 0; if (r1 > 9) r1 = 9;

    // h_v = silu(g0*Wv1[r0] + g1*Wv1[r1])
    float hv[16];
    #pragma unroll
    for (int j = 0; j < 16; j++) {
        float z = g0 * __ldg(&Wv1[r0 * 16 + j]) + g1 * __ldg(&Wv1[r1 * 16 + j]);
        hv[j] = siluf(z);
    }
    float* row = g_hy + (size_t)i * 40;
    #pragma unroll
    for (int q4 = 0; q4 < 4; q4++)
        ((float4*)row)[q4] = make_float4(hv[q4 * 4 + 0], hv[q4 * 4 + 1],
                                         hv[q4 * 4 + 2], hv[q4 * 4 + 3]);

    // y = [x0[src], x1dot]
    float y[24];
    float rinv = __frcp_rn(elen);
    #pragma unroll
    for (int u = 0; u < 16; u++) y[u] = x[s * 40 + u];
    #pragma unroll
    for (int u = 0; u < 8; u++) {
        const float* xp = x + s * 40 + 16 + u * 3;
        y[16 + u] = (xp[0] * ev0 + xp[1] * ev1 + xp[2] * ev2) * rinv;
    }
    #pragma unroll
    for (int q4 = 0; q4 < 6; q4++)
        ((float4*)(row + 16))[q4] = make_float4(y[q4 * 4 + 0], y[q4 * 4 + 1],
                                                y[q4 * 4 + 2], y[q4 * 4 + 3]);

    // logits = sum_j h_k[j] * (R[dst][j] . y)
    float lg = 0.f;
    const float4* Rp = (const float4*)(g_R + (size_t)d * 384);
    #pragma unroll
    for (int j = 0; j < 16; j++) {
        float zk = g0 * __ldg(&Wk1[r0 * 16 + j]) + g1 * __ldg(&Wk1[r1 * 16 + j]);
        float hk = siluf(zk);
        float Sj = 0.f;
        #pragma unroll
        for (int q4 = 0; q4 < 6; q4++) {
            float4 r4 = __ldg(&Rp[j * 6 + q4]);
            Sj += r4.x * y[q4 * 4 + 0] + r4.y * y[q4 * 4 + 1]
                + r4.z * y[q4 * 4 + 2] + r4.w * y[q4 * 4 + 3];
        }
        lg += hk * Sj;
    }
    g_expv[i] = wcut * __expf(lg);
}

// ---------------- pass B + output: warp per dst node ----------------
// T entries: t = l + 32k, k=0..11; t = u*16 + j with j = l&15, u = (l>>4) + 2k
__global__ void k_passB(const float* __restrict__ Wv2, float* __restrict__ out) {
    __shared__ float Ts[8][384];
    int wwarp = threadIdx.x >> 5;
    int l = threadIdx.x & 31;
    int n = blockIdx.x * 8 + wwarp;
    if (n >= N_NODESC) return;
    int beg = g_off[n], end = g_off[n + 1];

    float z = 0.f;
    for (int i = beg; i < end; i++) z += g_expv[i];
    if (z == 0.f) z = 1.f;
    float zinv = __fdividef(1.f, z);

    float acc[12];
    #pragma unroll
    for (int k = 0; k < 12; k++) acc[k] = 0.f;
    int par = l >> 4;
    int jj = l & 15;

    for (int i = beg; i < end; i++) {
        float evv = g_expv[i];          // warp-uniform
        if (evv > 0.f) {
            float sal = sqrtf(evv * zinv);
            const float* row = g_hy + (size_t)i * 40;
            float A = row[l];                       // lanes 0..15: hv, 16..31: y[0..15]
            float B = (l < 8) ? row[32 + l] : 0.f;  // y[16..23]
            float hval = __shfl_sync(0xffffffffu, A, jj);
            float sh = sal * hval;
            #pragma unroll
            for (int k = 0; k < 8; k++) {           // u = par + 2k < 16
                float yv = __shfl_sync(0xffffffffu, A, 16 + par + 2 * k);
                acc[k] += sh * yv;
            }
            #pragma unroll
            for (int k = 8; k < 12; k++) {          // u = par + 2k >= 16
                float yv = __shfl_sync(0xffffffffu, B, par + 2 * k - 16);
                acc[k] += sh * yv;
            }
        }
    }

    #pragma unroll
    for (int k = 0; k < 12; k++) Ts[wwarp][l + 32 * k] = acc[k];
    __syncwarp();

    // out[n][l] = c_v * sum_{t} Ts[t] * Wv2[j*768 + u*32 + l],  t = u*16+j
    float o = 0.f;
    #pragma unroll 8
    for (int t = 0; t < 384; t++) {
        int u = t >> 4, j = t & 15;
        o += Ts[wwarp][t] * __ldg(&Wv2[j * 768 + u * 32 + l]);
    }
    out[n * 32 + l] = o * C_V;
}

// ---------------- launch ----------------
extern "C" void kernel_launch(void* const* d_in, const int* in_sizes, int n_in,
                              void* d_out, int out_size) {
    (void)in_sizes; (void)n_in; (void)out_size;
    const float* x    = (const float*)d_in[0];
    const float* pos  = (const float*)d_in[1];
    const float* Wq   = (const float*)d_in[2];
    const float* Wk1  = (const float*)d_in[3];
    const float* Wk2  = (const float*)d_in[4];
    const float* Wv1  = (const float*)d_in[5];
    const float* Wv2  = (const float*)d_in[6];
    const float* Wdot = (const float*)d_in[7];
    const int* esrc   = (const int*)d_in[8];
    const int* edst   = (const int*)d_in[9];
    float* out = (float*)d_out;

    k_zero<<<(N_NODESC + 255) / 256, 256>>>();
    k_hist<<<(N_EDGESC + 255) / 256, 256>>>(edst);
    k_scan<<<1, 1024>>>();
    k_scatter<<<(N_EDGESC + 255) / 256, 256>>>(edst);
    k_qd<<<(N_NODESC + 127) / 128, 128>>>(x, Wq, Wdot);
    k_R<<<N_NODESC, 384>>>(Wk2);
    k_passA<<<(N_EDGESC + 127) / 128, 128>>>(x, pos, Wk1, Wv1, esrc, edst);
    k_passB<<<N_NODESC / 8, 256>>>(Wv2, out);
}

// round 2
// speedup vs baseline: 1.0555x; 1.0555x over previous
#include <cuda_runtime.h>
#include <math.h>

#define N_NODESC 20000
#define N_EDGESC 120000

// ---- static device scratch ----
__device__ int   g_deg[N_NODESC];
__device__ int   g_off[N_NODESC + 1];
__device__ int   g_cursor[N_NODESC];
__device__ int2  g_edge[N_EDGESC];           // sorted (src,dst)
__device__ float g_qd[N_NODESC * 16];
__device__ float g_R[N_NODESC * 384];        // R[n][j*24+u]
__device__ float g_expv[N_EDGESC];
__device__ float g_hy[N_EDGESC * 40];        // h_v[16], y[24] per sorted slot
__device__ float g_T[(size_t)N_NODESC * 384]; // T[n][t], t = u*16+j

#define C_EMB   8.4335730690754870f     // 1.14136 * e^2
#define C_V     0.05103103630798287f    // 1/(4*sqrt(24))
#define C_LOGIT 0.003189439769248930f   // 1/(64*sqrt(24))

__device__ __forceinline__ float susf(float v) {
    return (v > 0.f) ? __expf(-__fdividef(1.f, v)) : 0.f;
}
__device__ __forceinline__ float siluf(float z) {
    return __fdividef(z, 1.f + __expf(-z));
}

// ---------------- init: zero deg + qd ----------------
__global__ void k_init(const float* __restrict__ x,
                       const float* __restrict__ Wq,
                       const float* __restrict__ Wdot) {
    int n = blockIdx.x * blockDim.x + threadIdx.x;
    if (n >= N_NODESC) return;
    g_deg[n] = 0;
    float x0[16], q[16];
    #pragma unroll
    for (int u = 0; u < 16; u++) x0[u] = x[n * 40 + u];
    #pragma unroll
    for (int w = 0; w < 16; w++) {
        float a = 0.f;
        #pragma unroll
        for (int u = 0; u < 16; u++) a += x0[u] * __ldg(&Wq[u * 16 + w]);
        q[w] = a * 0.25f;
    }
    #pragma unroll
    for (int w = 0; w < 16; w++) {
        float a = 0.f;
        #pragma unroll
        for (int u = 0; u < 16; u++) a += q[u] * __ldg(&Wdot[u * 16 + w]);
        g_qd[n * 16 + w] = a * C_LOGIT;
    }
}

__global__ void k_hist(const int* __restrict__ dst) {
    int i = blockIdx.x * blockDim.x + threadIdx.x;
    if (i < N_EDGESC) atomicAdd(&g_deg[dst[i]], 1);
}

__global__ void k_scan() {
    __shared__ int s[1024];
    int tid = threadIdx.x;
    const int CH = (N_NODESC + 1023) / 1024;  // 20
    int base = tid * CH;
    int sum = 0;
    #pragma unroll
    for (int c = 0; c < CH; c++) {
        int idx = base + c;
        if (idx < N_NODESC) sum += g_deg[idx];
    }
    s[tid] = sum;
    __syncthreads();
    for (int d = 1; d < 1024; d <<= 1) {
        int v = (tid >= d) ? s[tid - d] : 0;
        __syncthreads();
        s[tid] += v;
        __syncthreads();
    }
    int run = s[tid] - sum;
    for (int c = 0; c < CH; c++) {
        int idx = base + c;
        if (idx < N_NODESC) {
            g_off[idx] = run;
            g_cursor[idx] = run;
            run += g_deg[idx];
        }
    }
    if (tid == 1023) g_off[N_NODESC] = s[1023];
}

// ---------------- fused scatter + R ----------------
#define R_BLOCKS  N_NODESC
#define SC_BLOCKS ((N_EDGESC + 383) / 384)

__global__ void k_scatterR(const float* __restrict__ Wk2,
                           const int* __restrict__ src,
                           const int* __restrict__ dst) {
    int bid = blockIdx.x;
    int t = threadIdx.x;
    if (bid < R_BLOCKS) {
        __shared__ float qs[16];
        if (t < 16) qs[t] = g_qd[bid * 16 + t];
        __syncthreads();
        int j = t / 24;
        int u = t - j * 24;
        const float* w = Wk2 + j * 384 + u * 16;
        float a = 0.f;
        #pragma unroll
        for (int k = 0; k < 16; k++) a += __ldg(&w[k]) * qs[k];
        g_R[(size_t)bid * 384 + t] = a;
    } else {
        int i = (bid - R_BLOCKS) * 384 + t;
        if (i < N_EDGESC) {
            int d = dst[i];
            int p = atomicAdd(&g_cursor[d], 1);
            g_edge[p] = make_int2(src[i], d);
        }
    }
}

// ---------------- pass A ----------------
__global__ void k_passA(const float* __restrict__ x, const float* __restrict__ pos,
                        const float* __restrict__ Wk1, const float* __restrict__ Wv1) {
    int i = blockIdx.x * blockDim.x + threadIdx.x;
    if (i >= N_EDGESC) return;
    int2 sd = g_edge[i];
    int s = sd.x, d = sd.y;

    float ev0 = pos[s * 3 + 0] - pos[d * 3 + 0];
    float ev1 = pos[s * 3 + 1] - pos[d * 3 + 1];
    float ev2 = pos[s * 3 + 2] - pos[d * 3 + 2];
    float elen = sqrtf(ev0 * ev0 + ev1 * ev1 + ev2 * ev2 + 1e-12f);

    float wcut = susf(10.f * (1.f - elen * 0.25f));
    if (!(wcut > 0.f)) { g_expv[i] = 0.f; return; }

    float tt = elen * 2.75f;
    int b0 = (int)tt;
    float d0 = tt - (float)b0;
    float g0 = (b0 >= 1 && b0 <= 10) ? (C_EMB * susf(d0 + 1.f) * susf(1.f - d0)) : 0.f;
    float g1 = (b0 >= 0 && b0 <= 9)  ? (C_EMB * susf(d0) * susf(2.f - d0)) : 0.f;
    int r0 = b0 - 1; if (r0 < 0) r0 = 0; if (r0 > 9) r0 = 9;
    int r1 = b0;     if (r1 < 0) r1 = 0; if (r1 > 9) r1 = 9;

    // x row as float4s
    float4 xr[10];
    const float4* xp4 = (const float4*)(x + (size_t)s * 40);
    #pragma unroll
    for (int q = 0; q < 10; q++) xr[q] = __ldg(&xp4[q]);
    const float* xf = (const float*)xr;

    float y[24];
    float rinv = __frcp_rn(elen);
    #pragma unroll
    for (int u = 0; u < 16; u++) y[u] = xf[u];
    #pragma unroll
    for (int u = 0; u < 8; u++) {
        y[16 + u] = (xf[16 + u * 3] * ev0 + xf[17 + u * 3] * ev1 + xf[18 + u * 3] * ev2) * rinv;
    }

    // h_v -> g_hy
    float* row = g_hy + (size_t)i * 40;
    #pragma unroll
    for (int j4 = 0; j4 < 4; j4++) {
        float h0 = siluf(g0 * __ldg(&Wv1[r0 * 16 + j4 * 4 + 0]) + g1 * __ldg(&Wv1[r1 * 16 + j4 * 4 + 0]));
        float h1 = siluf(g0 * __ldg(&Wv1[r0 * 16 + j4 * 4 + 1]) + g1 * __ldg(&Wv1[r1 * 16 + j4 * 4 + 1]));
        float h2 = siluf(g0 * __ldg(&Wv1[r0 * 16 + j4 * 4 + 2]) + g1 * __ldg(&Wv1[r1 * 16 + j4 * 4 + 2]));
        float h3 = siluf(g0 * __ldg(&Wv1[r0 * 16 + j4 * 4 + 3]) + g1 * __ldg(&Wv1[r1 * 16 + j4 * 4 + 3]));
        ((float4*)row)[j4] = make_float4(h0, h1, h2, h3);
    }
    #pragma unroll
    for (int q4 = 0; q4 < 6; q4++)
        ((float4*)(row + 16))[q4] = make_float4(y[q4 * 4 + 0], y[q4 * 4 + 1],
                                                y[q4 * 4 + 2], y[q4 * 4 + 3]);

    // logits = sum_j h_k[j] * (R[d][j] . y)
    float lg = 0.f;
    const float4* Rp = (const float4*)(g_R + (size_t)d * 384);
    #pragma unroll
    for (int j = 0; j < 16; j++) {
        float zk = g0 * __ldg(&Wk1[r0 * 16 + j]) + g1 * __ldg(&Wk1[r1 * 16 + j]);
        float hk = siluf(zk);
        float Sj = 0.f;
        #pragma unroll
        for (int q4 = 0; q4 < 6; q4++) {
            float4 r4 = __ldg(&Rp[j * 6 + q4]);
            Sj += r4.x * y[q4 * 4 + 0] + r4.y * y[q4 * 4 + 1]
                + r4.z * y[q4 * 4 + 2] + r4.w * y[q4 * 4 + 3];
        }
        lg += hk * Sj;
    }
    g_expv[i] = wcut * __expf(lg);
}

// ---------------- pass B: warp per node, write T ----------------
// acc[k] holds T[t] with t = l + 32k  (== u*16+j, j=l&15, u=(l>>4)+2k = t>>4)
__global__ void k_passB() {
    int wwarp = threadIdx.x >> 5;
    int l = threadIdx.x & 31;
    int n = blockIdx.x * 8 + wwarp;
    if (n >= N_NODESC) return;
    int beg = g_off[n], end = g_off[n + 1];

    float z = 0.f;
    for (int i = beg; i < end; i++) z += g_expv[i];
    if (z == 0.f) z = 1.f;
    float zinv = __fdividef(1.f, z);

    float acc[12];
    #pragma unroll
    for (int k = 0; k < 12; k++) acc[k] = 0.f;
    int par = l >> 4;
    int jj = l & 15;

    for (int i = beg; i < end; i++) {
        float evv = g_expv[i];
        if (evv > 0.f) {
            float sal = sqrtf(evv * zinv);
            const float* row = g_hy + (size_t)i * 40;
            float A = row[l];                       // lanes 0..15: hv, 16..31: y[0..15]
            float B = (l < 8) ? row[32 + l] : 0.f;  // y[16..23]
            float hval = __shfl_sync(0xffffffffu, A, jj);
            float sh = sal * hval;
            #pragma unroll
            for (int k = 0; k < 8; k++) {
                float yv = __shfl_sync(0xffffffffu, A, 16 + par + 2 * k);
                acc[k] += sh * yv;
            }
            #pragma unroll
            for (int k = 8; k < 12; k++) {
                float yv = __shfl_sync(0xffffffffu, B, par + 2 * k - 16);
                acc[k] += sh * yv;
            }
        }
    }

    float* Tp = g_T + (size_t)n * 384;
    #pragma unroll
    for (int k = 0; k < 12; k++) Tp[l + 32 * k] = acc[k];
}

// ---------------- output GEMM: out = C_V * T @ W' ----------------
// W'[t][col] = Wv2[(t&15)*768 + (t>>4)*32 + col]
__global__ void k_out(const float* __restrict__ Wv2, float* __restrict__ out) {
    __shared__ float sW[32 * 32];       // W chunk [32 k][32 col]
    __shared__ float sT[64][33];        // T tile  [64 node][32 k]
    int t = threadIdx.x;                // 256 threads
    int base = blockIdx.x * 64;
    int tx = t & 15, ty = t >> 4;       // cols {tx, tx+16}, nodes {ty*4..ty*4+3}
    int lrow = t >> 5, lcol = t & 31;

    float acc[4][2] = {{0.f,0.f},{0.f,0.f},{0.f,0.f},{0.f,0.f}};

    for (int kc = 0; kc < 12; kc++) {
        __syncthreads();
        // load W chunk: k = kc*32 + (i>>5), col = i&31
        #pragma unroll
        for (int q = 0; q < 4; q++) {
            int i = q * 256 + t;
            int k = kc * 32 + (i >> 5);
            int col = i & 31;
            sW[i] = __ldg(&Wv2[(k & 15) * 768 + (k >> 4) * 32 + col]);
        }
        // load T tile
        #pragma unroll
        for (int r = 0; r < 8; r++) {
            int rowi = r * 8 + lrow;
            int n = base + rowi;
            sT[rowi][lcol] = (n < N_NODESC) ? g_T[(size_t)n * 384 + kc * 32 + lcol] : 0.f;
        }
        __syncthreads();
        #pragma unroll
        for (int kk = 0; kk < 32; kk++) {
            float w0 = sW[kk * 32 + tx];
            float w1 = sW[kk * 32 + tx + 16];
            #pragma unroll
            for (int i2 = 0; i2 < 4; i2++) {
                float tv = sT[ty * 4 + i2][kk];
                acc[i2][0] += tv * w0;
                acc[i2][1] += tv * w1;
            }
        }
    }
    #pragma unroll
    for (int i2 = 0; i2 < 4; i2++) {
        int n = base + ty * 4 + i2;
        if (n < N_NODESC) {
            out[n * 32 + tx]      = acc[i2][0] * C_V;
            out[n * 32 + tx + 16] = acc[i2][1] * C_V;
        }
    }
}

// ---------------- launch ----------------
extern "C" void kernel_launch(void* const* d_in, const int* in_sizes, int n_in,
                              void* d_out, int out_size) {
    (void)in_sizes; (void)n_in; (void)out_size;
    const float* x    = (const float*)d_in[0];
    const float* pos  = (const float*)d_in[1];
    const float* Wq   = (const float*)d_in[2];
    const float* Wk1  = (const float*)d_in[3];
    const float* Wk2  = (const float*)d_in[4];
    const float* Wv1  = (const float*)d_in[5];
    const float* Wv2  = (const float*)d_in[6];
    const float* Wdot = (const float*)d_in[7];
    const int* esrc   = (const int*)d_in[8];
    const int* edst   = (const int*)d_in[9];
    float* out = (float*)d_out;

    k_init<<<(N_NODESC + 255) / 256, 256>>>(x, Wq, Wdot);
    k_hist<<<(N_EDGESC + 255) / 256, 256>>>(edst);
    k_scan<<<1, 1024>>>();
    k_scatterR<<<R_BLOCKS + SC_BLOCKS, 384>>>(Wk2, esrc, edst);
    k_passA<<<(N_EDGESC + 127) / 128, 128>>>(x, pos, Wk1, Wv1);
    k_passB<<<(N_NODESC + 7) / 8, 256>>>();
    k_out<<<(N_NODESC + 63) / 64, 256>>>(Wv2, out);
}

// round 3
// speedup vs baseline: 2.5568x; 2.4223x over previous
#include <cuda_runtime.h>
#include <math.h>

#define N_NODESC 20000
#define N_EDGESC 120000

// ---- static device scratch ----
__device__ int   g_deg[N_NODESC];
__device__ int   g_off[N_NODESC + 1];
__device__ int   g_cursor[N_NODESC];
__device__ int2  g_edge[N_EDGESC];            // sorted (src,dst)
__device__ float g_qd[N_NODESC * 16];
__device__ float g_R[(size_t)N_NODESC * 384]; // R[n][j*24+u]
__device__ float g_expv[N_EDGESC];
__device__ float g_hy[(size_t)N_EDGESC * 40]; // h_v[16], y[24] per sorted slot
__device__ float g_T[(size_t)N_NODESC * 384]; // T[n][t], t = u*16+j

#define C_EMB   8.4335730690754870f     // 1.14136 * e^2
#define C_V     0.05103103630798287f    // 1/(4*sqrt(24))
#define C_LOGIT 0.003189439769248930f   // 1/(64*sqrt(24))

__device__ __forceinline__ float susf(float v) {
    return (v > 0.f) ? __expf(-__fdividef(1.f, v)) : 0.f;
}
__device__ __forceinline__ float siluf(float z) {
    return __fdividef(z, 1.f + __expf(-z));
}

// ---------------- init: zero deg + qd ----------------
__global__ void k_init(const float* __restrict__ x,
                       const float* __restrict__ Wq,
                       const float* __restrict__ Wdot) {
    int n = blockIdx.x * blockDim.x + threadIdx.x;
    if (n >= N_NODESC) return;
    g_deg[n] = 0;
    float x0[16], q[16];
    #pragma unroll
    for (int u = 0; u < 16; u++) x0[u] = x[n * 40 + u];
    #pragma unroll
    for (int w = 0; w < 16; w++) {
        float a = 0.f;
        #pragma unroll
        for (int u = 0; u < 16; u++) a += x0[u] * __ldg(&Wq[u * 16 + w]);
        q[w] = a * 0.25f;
    }
    #pragma unroll
    for (int w = 0; w < 16; w++) {
        float a = 0.f;
        #pragma unroll
        for (int u = 0; u < 16; u++) a += q[u] * __ldg(&Wdot[u * 16 + w]);
        g_qd[n * 16 + w] = a * C_LOGIT;
    }
}

__global__ void k_hist(const int* __restrict__ dst) {
    int i = blockIdx.x * blockDim.x + threadIdx.x;
    if (i < N_EDGESC) atomicAdd(&g_deg[dst[i]], 1);
}

__global__ void k_scan() {
    __shared__ int s[1024];
    int tid = threadIdx.x;
    const int CH = (N_NODESC + 1023) / 1024;  // 20
    int base = tid * CH;
    int sum = 0;
    #pragma unroll
    for (int c = 0; c < CH; c++) {
        int idx = base + c;
        if (idx < N_NODESC) sum += g_deg[idx];
    }
    s[tid] = sum;
    __syncthreads();
    for (int d = 1; d < 1024; d <<= 1) {
        int v = (tid >= d) ? s[tid - d] : 0;
        __syncthreads();
        s[tid] += v;
        __syncthreads();
    }
    int run = s[tid] - sum;
    for (int c = 0; c < CH; c++) {
        int idx = base + c;
        if (idx < N_NODESC) {
            g_off[idx] = run;
            g_cursor[idx] = run;
            run += g_deg[idx];
        }
    }
    if (tid == 1023) g_off[N_NODESC] = s[1023];
}

__global__ void k_scatter(const int* __restrict__ src, const int* __restrict__ dst) {
    int i = blockIdx.x * blockDim.x + threadIdx.x;
    if (i < N_EDGESC) {
        int d = dst[i];
        int p = atomicAdd(&g_cursor[d], 1);
        g_edge[p] = make_int2(src[i], d);
    }
}

// ---------------- R GEMM: R[n][t] = sum_w Wk2[j*384+u*16+w] * qd[n][w], t=j*24+u ----------------
#define RT_NODES 50
__global__ void k_R(const float* __restrict__ Wk2) {
    __shared__ float sW[16][385];          // sW[w][j*24+u], padded
    __shared__ float sq[RT_NODES * 16];    // qd tile
    int t = threadIdx.x;                   // 0..383

    // stage Wk2, coalesced: g = it*384 + t -> j=it, u=t/16, w=t%16
    #pragma unroll
    for (int it = 0; it < 16; it++) {
        float v = __ldg(&Wk2[it * 384 + t]);
        sW[t & 15][it * 24 + (t >> 4)] = v;
    }
    // stage qd tile (800 floats)
    int nb = blockIdx.x * RT_NODES;
    for (int i = t; i < RT_NODES * 16; i += 384)
        sq[i] = g_qd[nb * 16 + i];
    __syncthreads();

    // hoist this thread's weight column to registers
    float wr[16];
    #pragma unroll
    for (int w = 0; w < 16; w++) wr[w] = sW[w][t];

    float* Rp = g_R + (size_t)nb * 384 + t;
    #pragma unroll 2
    for (int n0 = 0; n0 < RT_NODES; n0++) {
        const float4* q4 = (const float4*)(sq + n0 * 16);
        float4 qa = q4[0], qb = q4[1], qc = q4[2], qdv = q4[3];
        float a = wr[0] * qa.x + wr[1] * qa.y + wr[2] * qa.z + wr[3] * qa.w
                + wr[4] * qb.x + wr[5] * qb.y + wr[6] * qb.z + wr[7] * qb.w
                + wr[8] * qc.x + wr[9] * qc.y + wr[10] * qc.z + wr[11] * qc.w
                + wr[12] * qdv.x + wr[13] * qdv.y + wr[14] * qdv.z + wr[15] * qdv.w;
        Rp[(size_t)n0 * 384] = a;
    }
}

// ---------------- pass A ----------------
__global__ void k_passA(const float* __restrict__ x, const float* __restrict__ pos,
                        const float* __restrict__ Wk1, const float* __restrict__ Wv1) {
    int i = blockIdx.x * blockDim.x + threadIdx.x;
    if (i >= N_EDGESC) return;
    int2 sd = g_edge[i];
    int s = sd.x, d = sd.y;

    float ev0 = pos[s * 3 + 0] - pos[d * 3 + 0];
    float ev1 = pos[s * 3 + 1] - pos[d * 3 + 1];
    float ev2 = pos[s * 3 + 2] - pos[d * 3 + 2];
    float elen = sqrtf(ev0 * ev0 + ev1 * ev1 + ev2 * ev2 + 1e-12f);

    float wcut = susf(10.f * (1.f - elen * 0.25f));
    if (!(wcut > 0.f)) { g_expv[i] = 0.f; return; }

    float tt = elen * 2.75f;
    int b0 = (int)tt;
    float d0 = tt - (float)b0;
    float g0 = (b0 >= 1 && b0 <= 10) ? (C_EMB * susf(d0 + 1.f) * susf(1.f - d0)) : 0.f;
    float g1 = (b0 >= 0 && b0 <= 9)  ? (C_EMB * susf(d0) * susf(2.f - d0)) : 0.f;
    int r0 = b0 - 1; if (r0 < 0) r0 = 0; if (r0 > 9) r0 = 9;
    int r1 = b0;     if (r1 < 0) r1 = 0; if (r1 > 9) r1 = 9;

    float4 xr[10];
    const float4* xp4 = (const float4*)(x + (size_t)s * 40);
    #pragma unroll
    for (int q = 0; q < 10; q++) xr[q] = __ldg(&xp4[q]);
    const float* xf = (const float*)xr;

    float y[24];
    float rinv = __frcp_rn(elen);
    #pragma unroll
    for (int u = 0; u < 16; u++) y[u] = xf[u];
    #pragma unroll
    for (int u = 0; u < 8; u++) {
        y[16 + u] = (xf[16 + u * 3] * ev0 + xf[17 + u * 3] * ev1 + xf[18 + u * 3] * ev2) * rinv;
    }

    float* row = g_hy + (size_t)i * 40;
    #pragma unroll
    for (int j4 = 0; j4 < 4; j4++) {
        float h0 = siluf(g0 * __ldg(&Wv1[r0 * 16 + j4 * 4 + 0]) + g1 * __ldg(&Wv1[r1 * 16 + j4 * 4 + 0]));
        float h1 = siluf(g0 * __ldg(&Wv1[r0 * 16 + j4 * 4 + 1]) + g1 * __ldg(&Wv1[r1 * 16 + j4 * 4 + 1]));
        float h2 = siluf(g0 * __ldg(&Wv1[r0 * 16 + j4 * 4 + 2]) + g1 * __ldg(&Wv1[r1 * 16 + j4 * 4 + 2]));
        float h3 = siluf(g0 * __ldg(&Wv1[r0 * 16 + j4 * 4 + 3]) + g1 * __ldg(&Wv1[r1 * 16 + j4 * 4 + 3]));
        ((float4*)row)[j4] = make_float4(h0, h1, h2, h3);
    }
    #pragma unroll
    for (int q4 = 0; q4 < 6; q4++)
        ((float4*)(row + 16))[q4] = make_float4(y[q4 * 4 + 0], y[q4 * 4 + 1],
                                                y[q4 * 4 + 2], y[q4 * 4 + 3]);

    float lg = 0.f;
    const float4* Rp = (const float4*)(g_R + (size_t)d * 384);
    #pragma unroll
    for (int j = 0; j < 16; j++) {
        float zk = g0 * __ldg(&Wk1[r0 * 16 + j]) + g1 * __ldg(&Wk1[r1 * 16 + j]);
        float hk = siluf(zk);
        float Sj = 0.f;
        #pragma unroll
        for (int q4 = 0; q4 < 6; q4++) {
            float4 r4 = __ldg(&Rp[j * 6 + q4]);
            Sj += r4.x * y[q4 * 4 + 0] + r4.y * y[q4 * 4 + 1]
                + r4.z * y[q4 * 4 + 2] + r4.w * y[q4 * 4 + 3];
        }
        lg += hk * Sj;
    }
    g_expv[i] = wcut * __expf(lg);
}

// ---------------- pass B: warp per node, write T ----------------
__global__ void k_passB() {
    int wwarp = threadIdx.x >> 5;
    int l = threadIdx.x & 31;
    int n = blockIdx.x * 8 + wwarp;
    if (n >= N_NODESC) return;
    int beg = g_off[n], end = g_off[n + 1];

    float z = 0.f;
    for (int i = beg; i < end; i++) z += g_expv[i];
    if (z == 0.f) z = 1.f;
    float zinv = __fdividef(1.f, z);

    float acc[12];
    #pragma unroll
    for (int k = 0; k < 12; k++) acc[k] = 0.f;
    int par = l >> 4;
    int jj = l & 15;

    for (int i = beg; i < end; i++) {
        float evv = g_expv[i];
        if (evv > 0.f) {
            float sal = sqrtf(evv * zinv);
            const float* row = g_hy + (size_t)i * 40;
            float A = row[l];
            float B = (l < 8) ? row[32 + l] : 0.f;
            float hval = __shfl_sync(0xffffffffu, A, jj);
            float sh = sal * hval;
            #pragma unroll
            for (int k = 0; k < 8; k++) {
                float yv = __shfl_sync(0xffffffffu, A, 16 + par + 2 * k);
                acc[k] += sh * yv;
            }
            #pragma unroll
            for (int k = 8; k < 12; k++) {
                float yv = __shfl_sync(0xffffffffu, B, par + 2 * k - 16);
                acc[k] += sh * yv;
            }
        }
    }

    float* Tp = g_T + (size_t)n * 384;
    #pragma unroll
    for (int k = 0; k < 12; k++) Tp[l + 32 * k] = acc[k];
}

// ---------------- output GEMM: out = C_V * T @ W' ----------------
__global__ void k_out(const float* __restrict__ Wv2, float* __restrict__ out) {
    __shared__ float sW[32 * 32];
    __shared__ float sT[64][33];
    int t = threadIdx.x;
    int base = blockIdx.x * 64;
    int tx = t & 15, ty = t >> 4;
    int lrow = t >> 5, lcol = t & 31;

    float acc[4][2] = {{0.f,0.f},{0.f,0.f},{0.f,0.f},{0.f,0.f}};

    for (int kc = 0; kc < 12; kc++) {
        __syncthreads();
        #pragma unroll
        for (int q = 0; q < 4; q++) {
            int i = q * 256 + t;
            int k = kc * 32 + (i >> 5);
            int col = i & 31;
            sW[i] = __ldg(&Wv2[(k & 15) * 768 + (k >> 4) * 32 + col]);
        }
        #pragma unroll
        for (int r = 0; r < 8; r++) {
            int rowi = r * 8 + lrow;
            int n = base + rowi;
            sT[rowi][lcol] = (n < N_NODESC) ? g_T[(size_t)n * 384 + kc * 32 + lcol] : 0.f;
        }
        __syncthreads();
        #pragma unroll
        for (int kk = 0; kk < 32; kk++) {
            float w0 = sW[kk * 32 + tx];
            float w1 = sW[kk * 32 + tx + 16];
            #pragma unroll
            for (int i2 = 0; i2 < 4; i2++) {
                float tv = sT[ty * 4 + i2][kk];
                acc[i2][0] += tv * w0;
                acc[i2][1] += tv * w1;
            }
        }
    }
    #pragma unroll
    for (int i2 = 0; i2 < 4; i2++) {
        int n = base + ty * 4 + i2;
        if (n < N_NODESC) {
            out[n * 32 + tx]      = acc[i2][0] * C_V;
            out[n * 32 + tx + 16] = acc[i2][1] * C_V;
        }
    }
}

// ---------------- launch ----------------
extern "C" void kernel_launch(void* const* d_in, const int* in_sizes, int n_in,
                              void* d_out, int out_size) {
    (void)in_sizes; (void)n_in; (void)out_size;
    const float* x    = (const float*)d_in[0];
    const float* pos  = (const float*)d_in[1];
    const float* Wq   = (const float*)d_in[2];
    const float* Wk1  = (const float*)d_in[3];
    const float* Wk2  = (const float*)d_in[4];
    const float* Wv1  = (const float*)d_in[5];
    const float* Wv2  = (const float*)d_in[6];
    const float* Wdot = (const float*)d_in[7];
    const int* esrc   = (const int*)d_in[8];
    const int* edst   = (const int*)d_in[9];
    float* out = (float*)d_out;

    k_init<<<(N_NODESC + 255) / 256, 256>>>(x, Wq, Wdot);
    k_hist<<<(N_EDGESC + 255) / 256, 256>>>(edst);
    k_scan<<<1, 1024>>>();
    k_scatter<<<(N_EDGESC + 255) / 256, 256>>>(esrc, edst);
    k_R<<<N_NODESC / RT_NODES, 384>>>(Wk2);
    k_passA<<<(N_EDGESC + 127) / 128, 128>>>(x, pos, Wk1, Wv1);
    k_passB<<<(N_NODESC + 7) / 8, 256>>>();
    k_out<<<(N_NODESC + 63) / 64, 256>>>(Wv2, out);
}

// round 4
// speedup vs baseline: 2.6755x; 1.0464x over previous
#include <cuda_runtime.h>
#include <math.h>

#define N_NODESC 20000
#define N_EDGESC 120000
#define HY_STRIDE 44

// ---- static device scratch ----
__device__ int   g_deg[N_NODESC];
__device__ int   g_off[N_NODESC + 1];
__device__ int   g_cursor[N_NODESC];
__device__ int2  g_edge[N_EDGESC];                       // sorted (src,dst)
__device__ float g_MW[16 * 384];                         // MW[p][t], t=j*24+u
__device__ float g_R[(size_t)N_NODESC * 384];            // R[n][j*24+u]
__device__ float g_hy[(size_t)N_EDGESC * HY_STRIDE + 16];// hv'[16], y[24], expv, pad
__device__ float g_T[(size_t)N_NODESC * 384];            // T[n][t], t=u*16+j

#define C_EMB   8.4335730690754870f     // 1.14136 * e^2
#define C_V     0.05103103630798287f    // 1/(4*sqrt(24))
#define C_LOGIT 0.003189439769248930f   // 1/(64*sqrt(24))

__device__ __forceinline__ float susf(float v) {
    return (v > 0.f) ? __expf(-__fdividef(1.f, v)) : 0.f;
}
__device__ __forceinline__ float siluf(float z) {
    return __fdividef(z, 1.f + __expf(-z));
}

// ---------------- block 0: MW = (0.25*C_LOGIT * Wq@Wdot) @ Wk2'' ; blocks>=1: zero deg ----------------
__global__ void k_zeroprep(const float* __restrict__ Wq,
                           const float* __restrict__ Wdot,
                           const float* __restrict__ Wk2) {
    int t = threadIdx.x;  // 384
    if (blockIdx.x == 0) {
        __shared__ float M[16][17];
        if (t < 256) {
            int p = t >> 4, w = t & 15;
            float a = 0.f;
            #pragma unroll
            for (int r = 0; r < 16; r++) a += __ldg(&Wq[p * 16 + r]) * __ldg(&Wdot[r * 16 + w]);
            M[p][w] = a * 0.25f * C_LOGIT;
        }
        __syncthreads();
        int j = t / 24;
        int u = t - j * 24;
        float wk[16];
        #pragma unroll
        for (int w = 0; w < 16; w++) wk[w] = __ldg(&Wk2[j * 384 + u * 16 + w]);
        #pragma unroll
        for (int p = 0; p < 16; p++) {
            float a = 0.f;
            #pragma unroll
            for (int w = 0; w < 16; w++) a += M[p][w] * wk[w];
            g_MW[p * 384 + t] = a;
        }
    } else {
        int i = (blockIdx.x - 1) * 384 + t;
        if (i < N_NODESC) g_deg[i] = 0;
    }
}

__global__ void k_hist(const int* __restrict__ dst) {
    int i = blockIdx.x * blockDim.x + threadIdx.x;
    if (i < N_EDGESC) atomicAdd(&g_deg[dst[i]], 1);
}

__global__ void k_scan() {
    __shared__ int s[1024];
    int tid = threadIdx.x;
    const int CH = (N_NODESC + 1023) / 1024;  // 20
    int base = tid * CH;
    int sum = 0;
    #pragma unroll
    for (int c = 0; c < CH; c++) {
        int idx = base + c;
        if (idx < N_NODESC) sum += g_deg[idx];
    }
    s[tid] = sum;
    __syncthreads();
    for (int d = 1; d < 1024; d <<= 1) {
        int v = (tid >= d) ? s[tid - d] : 0;
        __syncthreads();
        s[tid] += v;
        __syncthreads();
    }
    int run = s[tid] - sum;
    for (int c = 0; c < CH; c++) {
        int idx = base + c;
        if (idx < N_NODESC) {
            g_off[idx] = run;
            g_cursor[idx] = run;
            run += g_deg[idx];
        }
    }
    if (tid == 1023) g_off[N_NODESC] = s[1023];
}

__global__ void k_scatter(const int* __restrict__ src, const int* __restrict__ dst) {
    int i = blockIdx.x * blockDim.x + threadIdx.x;
    if (i < N_EDGESC) {
        int d = dst[i];
        int p = atomicAdd(&g_cursor[d], 1);
        g_edge[p] = make_int2(src[i], d);
    }
}

// ---------------- R GEMM: R[n][t] = sum_p x0[n][p] * MW[p][t] ----------------
#define RT_NODES 50
__global__ void k_R(const float* __restrict__ x) {
    __shared__ float sW[16][385];          // sW[p][t]
    __shared__ float sq[RT_NODES * 16];    // x0 tile
    int t = threadIdx.x;                   // 0..383

    #pragma unroll
    for (int p = 0; p < 16; p++) sW[p][t] = g_MW[p * 384 + t];

    int nb = blockIdx.x * RT_NODES;
    for (int i = t; i < RT_NODES * 16; i += 384) {
        int n = i >> 4, c = i & 15;
        sq[i] = x[(size_t)(nb + n) * 40 + c];
    }
    __syncthreads();

    float wr[16];
    #pragma unroll
    for (int p = 0; p < 16; p++) wr[p] = sW[p][t];

    float* Rp = g_R + (size_t)nb * 384 + t;
    #pragma unroll 2
    for (int n0 = 0; n0 < RT_NODES; n0++) {
        const float4* q4 = (const float4*)(sq + n0 * 16);
        float4 qa = q4[0], qb = q4[1], qc = q4[2], qdv = q4[3];
        float a = wr[0] * qa.x + wr[1] * qa.y + wr[2] * qa.z + wr[3] * qa.w
                + wr[4] * qb.x + wr[5] * qb.y + wr[6] * qb.z + wr[7] * qb.w
                + wr[8] * qc.x + wr[9] * qc.y + wr[10] * qc.z + wr[11] * qc.w
                + wr[12] * qdv.x + wr[13] * qdv.y + wr[14] * qdv.z + wr[15] * qdv.w;
        Rp[(size_t)n0 * 384] = a;
    }
}

// ---------------- pass A: hv' = sqrt(expv)*hv, y, expv packed per edge ----------------
__global__ void k_passA(const float* __restrict__ x, const float* __restrict__ pos,
                        const float* __restrict__ Wk1, const float* __restrict__ Wv1) {
    int i = blockIdx.x * blockDim.x + threadIdx.x;
    if (i >= N_EDGESC) return;
    int2 sd = g_edge[i];
    int s = sd.x, d = sd.y;
    float* row = g_hy + (size_t)i * HY_STRIDE;

    float ev0 = pos[s * 3 + 0] - pos[d * 3 + 0];
    float ev1 = pos[s * 3 + 1] - pos[d * 3 + 1];
    float ev2 = pos[s * 3 + 2] - pos[d * 3 + 2];
    float elen = sqrtf(ev0 * ev0 + ev1 * ev1 + ev2 * ev2 + 1e-12f);

    float wcut = susf(10.f * (1.f - elen * 0.25f));
    if (!(wcut > 0.f)) {
        float4 z4 = make_float4(0.f, 0.f, 0.f, 0.f);
        ((float4*)row)[0] = z4; ((float4*)row)[1] = z4;
        ((float4*)row)[2] = z4; ((float4*)row)[3] = z4;
        ((float4*)row)[10] = z4;   // expv = 0
        return;
    }

    float tt = elen * 2.75f;
    int b0 = (int)tt;
    float d0 = tt - (float)b0;
    float g0 = (b0 >= 1 && b0 <= 10) ? (C_EMB * susf(d0 + 1.f) * susf(1.f - d0)) : 0.f;
    float g1 = (b0 >= 0 && b0 <= 9)  ? (C_EMB * susf(d0) * susf(2.f - d0)) : 0.f;
    int r0 = b0 - 1; if (r0 < 0) r0 = 0; if (r0 > 9) r0 = 9;
    int r1 = b0;     if (r1 < 0) r1 = 0; if (r1 > 9) r1 = 9;

    float4 xr[10];
    const float4* xp4 = (const float4*)(x + (size_t)s * 40);
    #pragma unroll
    for (int q = 0; q < 10; q++) xr[q] = __ldg(&xp4[q]);
    const float* xf = (const float*)xr;

    float y[24];
    float rinv = __frcp_rn(elen);
    #pragma unroll
    for (int u = 0; u < 16; u++) y[u] = xf[u];
    #pragma unroll
    for (int u = 0; u < 8; u++) {
        y[16 + u] = (xf[16 + u * 3] * ev0 + xf[17 + u * 3] * ev1 + xf[18 + u * 3] * ev2) * rinv;
    }

    // logits
    float lg = 0.f;
    const float4* Rp = (const float4*)(g_R + (size_t)d * 384);
    #pragma unroll
    for (int j = 0; j < 16; j++) {
        float zk = g0 * __ldg(&Wk1[r0 * 16 + j]) + g1 * __ldg(&Wk1[r1 * 16 + j]);
        float hk = siluf(zk);
        float Sj = 0.f;
        #pragma unroll
        for (int q4 = 0; q4 < 6; q4++) {
            float4 r4 = __ldg(&Rp[j * 6 + q4]);
            Sj += r4.x * y[q4 * 4 + 0] + r4.y * y[q4 * 4 + 1]
                + r4.z * y[q4 * 4 + 2] + r4.w * y[q4 * 4 + 3];
        }
        lg += hk * Sj;
    }
    float expv = wcut * __expf(lg);
    float sev = sqrtf(expv);

    // hv' = sev * silu(...)
    #pragma unroll
    for (int j4 = 0; j4 < 4; j4++) {
        float h0 = sev * siluf(g0 * __ldg(&Wv1[r0 * 16 + j4 * 4 + 0]) + g1 * __ldg(&Wv1[r1 * 16 + j4 * 4 + 0]));
        float h1 = sev * siluf(g0 * __ldg(&Wv1[r0 * 16 + j4 * 4 + 1]) + g1 * __ldg(&Wv1[r1 * 16 + j4 * 4 + 1]));
        float h2 = sev * siluf(g0 * __ldg(&Wv1[r0 * 16 + j4 * 4 + 2]) + g1 * __ldg(&Wv1[r1 * 16 + j4 * 4 + 2]));
        float h3 = sev * siluf(g0 * __ldg(&Wv1[r0 * 16 + j4 * 4 + 3]) + g1 * __ldg(&Wv1[r1 * 16 + j4 * 4 + 3]));
        ((float4*)row)[j4] = make_float4(h0, h1, h2, h3);
    }
    #pragma unroll
    for (int q4 = 0; q4 < 6; q4++)
        ((float4*)(row + 16))[q4] = make_float4(y[q4 * 4 + 0], y[q4 * 4 + 1],
                                                y[q4 * 4 + 2], y[q4 * 4 + 3]);
    ((float4*)row)[10] = make_float4(expv, 0.f, 0.f, 0.f);
}

// ---------------- pass B: single pass, warp per node ----------------
__global__ void k_passB() {
    int wwarp = threadIdx.x >> 5;
    int l = threadIdx.x & 31;
    int n = blockIdx.x * 8 + wwarp;
    if (n >= N_NODESC) return;
    int beg = g_off[n], end = g_off[n + 1];

    float acc[12];
    #pragma unroll
    for (int k = 0; k < 12; k++) acc[k] = 0.f;
    float z = 0.f;
    int par = l >> 4;
    int jj = l & 15;

    for (int i = beg; i < end; i++) {
        const float* row = g_hy + (size_t)i * HY_STRIDE;
        float A = row[l];                        // hv'[0..15], y[0..15]
        float B = (l < 16) ? row[32 + l] : 0.f;  // y[16..23], expv@8
        z += __shfl_sync(0xffffffffu, B, 8);
        float hval = __shfl_sync(0xffffffffu, A, jj);
        #pragma unroll
        for (int k = 0; k < 8; k++) {
            float yv = __shfl_sync(0xffffffffu, A, 16 + par + 2 * k);
            acc[k] += hval * yv;
        }
        #pragma unroll
        for (int k = 8; k < 12; k++) {
            float yv = __shfl_sync(0xffffffffu, B, par + 2 * k - 16);
            acc[k] += hval * yv;
        }
    }

    if (z == 0.f) z = 1.f;
    float sc = rsqrtf(z);
    float* Tp = g_T + (size_t)n * 384;
    #pragma unroll
    for (int k = 0; k < 12; k++) Tp[l + 32 * k] = acc[k] * sc;
}

// ---------------- output GEMM: out = C_V * T @ W', float4 inner ----------------
__global__ void k_out(const float* __restrict__ Wv2, float* __restrict__ out) {
    __shared__ __align__(16) float sW[32][36];    // [col][kk_local]
    __shared__ __align__(16) float sT[128][36];   // [node][kk_local]
    int t = threadIdx.x;                // 256
    int base = blockIdx.x * 128;
    int c0 = t & 15;
    int g = t >> 4;                     // node group: rows g*8 .. g*8+7

    float acc[8][2];
    #pragma unroll
    for (int i2 = 0; i2 < 8; i2++) { acc[i2][0] = 0.f; acc[i2][1] = 0.f; }

    for (int kc = 0; kc < 12; kc++) {
        __syncthreads();
        #pragma unroll
        for (int q = 0; q < 4; q++) {
            int i = q * 256 + t;
            int kkl = i >> 5, col = i & 31;
            int k = kc * 32 + kkl;
            sW[col][kkl] = __ldg(&Wv2[(k & 15) * 768 + (k >> 4) * 32 + col]);
        }
        #pragma unroll
        for (int q = 0; q < 16; q++) {
            int i = q * 256 + t;
            int node = i >> 5, kkl = i & 31;
            int n = base + node;
            sT[node][kkl] = (n < N_NODESC) ? g_T[(size_t)n * 384 + kc * 32 + kkl] : 0.f;
        }
        __syncthreads();
        #pragma unroll
        for (int kk4 = 0; kk4 < 8; kk4++) {
            float4 w0 = ((const float4*)sW[c0])[kk4];
            float4 w1 = ((const float4*)sW[c0 + 16])[kk4];
            #pragma unroll
            for (int i2 = 0; i2 < 8; i2++) {
                float4 tv = ((const float4*)sT[g * 8 + i2])[kk4];
                acc[i2][0] += tv.x * w0.x + tv.y * w0.y + tv.z * w0.z + tv.w * w0.w;
                acc[i2][1] += tv.x * w1.x + tv.y * w1.y + tv.z * w1.z + tv.w * w1.w;
            }
        }
    }
    #pragma unroll
    for (int i2 = 0; i2 < 8; i2++) {
        int n = base + g * 8 + i2;
        if (n < N_NODESC) {
            out[n * 32 + c0]      = acc[i2][0] * C_V;
            out[n * 32 + c0 + 16] = acc[i2][1] * C_V;
        }
    }
}

// ---------------- launch ----------------
extern "C" void kernel_launch(void* const* d_in, const int* in_sizes, int n_in,
                              void* d_out, int out_size) {
    (void)in_sizes; (void)n_in; (void)out_size;
    const float* x    = (const float*)d_in[0];
    const float* pos  = (const float*)d_in[1];
    const float* Wq   = (const float*)d_in[2];
    const float* Wk1  = (const float*)d_in[3];
    const float* Wk2  = (const float*)d_in[4];
    const float* Wv1  = (const float*)d_in[5];
    const float* Wv2  = (const float*)d_in[6];
    const float* Wdot = (const float*)d_in[7];
    const int* esrc   = (const int*)d_in[8];
    const int* edst   = (const int*)d_in[9];
    float* out = (float*)d_out;

    k_zeroprep<<<1 + (N_NODESC + 383) / 384, 384>>>(Wq, Wdot, Wk2);
    k_hist<<<(N_EDGESC + 255) / 256, 256>>>(edst);
    k_scan<<<1, 1024>>>();
    k_scatter<<<(N_EDGESC + 255) / 256, 256>>>(esrc, edst);
    k_R<<<N_NODESC / RT_NODES, 384>>>(x);
    k_passA<<<(N_EDGESC + 255) / 256, 256>>>(x, pos, Wk1, Wv1);
    k_passB<<<(N_NODESC + 7) / 8, 256>>>();
    k_out<<<(N_NODESC + 127) / 128, 256>>>(Wv2, out);
}